// round 7
// baseline (speedup 1.0000x reference)
#include <cuda_runtime.h>
#include <cuda_fp16.h>
#include <cstdint>

#define N_SEL   192
#define N_PTS   2048
#define C_IN    256
#define C_OUT   256
#define N_TILES 8

#define BM 64
#define BN 128
#define BK 32
#define NSLABS (C_IN / BK)   // 8
#define THREADS 256

#define ROWB   80            // tile row bytes: 32 fp16 (64B) + 16 pad

// dynamic smem layout
#define SM_BIAS  0                         // 128 f32 = 512 B (pad to 1024)
#define SM_AH    1024                      // 2 stages x 64 rows x 80 B
#define A_STG    (BM * ROWB)               // 5120
#define SM_B     (SM_AH + 2 * A_STG)       // 11264; 3 stages x 128 rows x 80 B
#define B_STG    (BN * ROWB)               // 10240
#define SM_TOTAL (SM_B + 3 * B_STG)        // 41984

// gathered, transposed fp16 weights: [n_sel][N=C_OUT][K=C_IN]
__device__ __half g_wt[(size_t)N_SEL * C_OUT * C_IN];

__device__ __forceinline__ uint32_t smem_u32(const void* p) {
    uint32_t a;
    asm("{ .reg .u64 t; cvta.to.shared.u64 t, %1; cvt.u32.u64 %0, t; }" : "=r"(a) : "l"(p));
    return a;
}
__device__ __forceinline__ void cp16(uint32_t dst, const void* src) {
    asm volatile("cp.async.cg.shared.global [%0], [%1], 16;" :: "r"(dst), "l"(src));
}
__device__ __forceinline__ uint32_t pack_h2(float a, float b) {
    uint32_t r;
    asm("cvt.rn.f16x2.f32 %0, %2, %1;" : "=r"(r) : "f"(a), "f"(b));
    return r;
}
__device__ __forceinline__ void ldmx4(uint32_t addr, uint32_t& r0, uint32_t& r1,
                                      uint32_t& r2, uint32_t& r3) {
    asm volatile("ldmatrix.sync.aligned.m8n8.x4.shared.b16 {%0,%1,%2,%3}, [%4];"
                 : "=r"(r0), "=r"(r1), "=r"(r2), "=r"(r3) : "r"(addr));
}
__device__ __forceinline__ void mma_f16(float* c, const uint32_t* a, const uint32_t* b) {
    asm volatile("mma.sync.aligned.m16n8k16.row.col.f32.f16.f16.f32 "
                 "{%0,%1,%2,%3}, {%4,%5,%6,%7}, {%8,%9}, {%0,%1,%2,%3};"
                 : "+f"(c[0]), "+f"(c[1]), "+f"(c[2]), "+f"(c[3])
                 : "r"(a[0]), "r"(a[1]), "r"(a[2]), "r"(a[3]), "r"(b[0]), "r"(b[1]));
}

// ---------------- kernel 1: gather + transpose + fp16 convert of W ----------------
__global__ void wt_prep_kernel(const float* __restrict__ weight,
                               const int* __restrict__ indices,
                               const int* __restrict__ t_ptr) {
    const int n = blockIdx.z;
    const int t = (t_ptr != nullptr) ? *t_ptr : 3;
    const int idx = indices[n];
    const float* W = weight + (((size_t)idx * N_TILES + t) * C_IN) * C_OUT; // [K][N]

    __shared__ float tile[32][33];
    const int tx = threadIdx.x;   // 0..31
    const int ty = threadIdx.y;   // 0..7
    const int kt = blockIdx.y * 32;
    const int nt = blockIdx.x * 32;

    #pragma unroll
    for (int j = 0; j < 4; j++) {
        const int k = kt + ty + j * 8;
        tile[ty + j * 8][tx] = W[(size_t)k * C_OUT + nt + tx];
    }
    __syncthreads();

    __half* o = g_wt + (size_t)n * C_OUT * C_IN;
    #pragma unroll
    for (int j = 0; j < 4; j++) {
        const int nn = nt + ty + j * 8;
        o[(size_t)nn * C_IN + kt + tx] = __float2half_rn(tile[tx][ty + j * 8]);
    }
}

// ---------------- kernel 2: fp16 mma.sync GEMM, 3 CTAs/SM ----------------
__global__ __launch_bounds__(THREADS, 3)
void gemm_f16_kernel(const float* __restrict__ x,
                     const float* __restrict__ bias,
                     const int* __restrict__ indices,
                     const int* __restrict__ t_ptr,
                     float* __restrict__ out) {
    extern __shared__ __align__(16) unsigned char smem[];
    const uint32_t sa = smem_u32(smem);

    const int tid  = threadIdx.x;
    const int lane = tid & 31;
    const int wid  = tid >> 5;          // 0..7

    const int n_sel  = blockIdx.z;
    const int m0     = blockIdx.x * BM;
    const int n_base = blockIdx.y * BN;
    const int t   = (t_ptr != nullptr) ? *t_ptr : 3;
    const int idx = indices[n_sel];

    const float* A = x + (size_t)n_sel * N_PTS * C_IN + (size_t)m0 * C_IN;
    const __half* Wn = g_wt + (size_t)n_sel * C_OUT * C_IN + (size_t)n_base * C_IN;

    // bias -> smem
    float* bs = (float*)(smem + SM_BIAS);
    if (tid < BN) bs[tid] = bias[((size_t)idx * N_TILES + t) * C_OUT + n_base + tid];

    // warp tiling: 2 m-warps x 4 n-warps; warp tile 32x32
    const int m_off = (wid >> 2) * 32;
    const int n_off = (wid & 3) * 32;

    float acc[2][4][4];
    #pragma unroll
    for (int i = 0; i < 2; i++)
        #pragma unroll
        for (int j = 0; j < 4; j++)
            #pragma unroll
            for (int q = 0; q < 4; q++)
                acc[i][j][q] = 0.0f;

    // per-thread A load mapping: 256 threads -> 64 rows x 32 cols (8 floats/thread)
    const int ar  = tid >> 2;            // row 0..63
    const int as8 = (tid & 3) * 8;       // col start (floats)

    // B cp.async mapping: 512 chunks of 16B (128 rows x 4 chunks)
    auto issue_B = [&](int s) {
        const uint32_t base = sa + SM_B + (uint32_t)(s % 3) * B_STG;
        const int k0 = s * BK;
        #pragma unroll
        for (int i = 0; i < 2; i++) {
            const int c = tid + i * THREADS;
            const int r = c >> 2, seg = c & 3;
            cp16(base + (uint32_t)(r * ROWB + seg * 16),
                 Wn + (size_t)r * C_IN + k0 + seg * 8);
        }
        asm volatile("cp.async.commit_group;" ::: "memory");
    };

    // prologue: A slab 0 into regs, B slab 0 in flight
    float4 a0, a1;
    {
        const float* src = A + (size_t)ar * C_IN + as8;
        a0 = *reinterpret_cast<const float4*>(src);
        a1 = *reinterpret_cast<const float4*>(src + 4);
    }
    issue_B(0);

    for (int s = 0; s < NSLABS; s++) {
        const int stgA = s & 1;

        // convert A regs -> fp16 smem (stage stgA)
        {
            const uint32_t off = (uint32_t)(SM_AH + stgA * A_STG + ar * ROWB + (as8 >> 3) * 16);
            uint4 v;
            v.x = pack_h2(a0.x, a0.y);
            v.y = pack_h2(a0.z, a0.w);
            v.z = pack_h2(a1.x, a1.y);
            v.w = pack_h2(a1.z, a1.w);
            *reinterpret_cast<uint4*>(smem + off) = v;
        }

        // prefetch slab s+1
        if (s + 1 < NSLABS) {
            const float* src = A + (size_t)ar * C_IN + (s + 1) * BK + as8;
            a0 = *reinterpret_cast<const float4*>(src);
            a1 = *reinterpret_cast<const float4*>(src + 4);
            issue_B(s + 1);
            asm volatile("cp.async.wait_group 1;" ::: "memory");
        } else {
            asm volatile("cp.async.wait_group 0;" ::: "memory");
        }
        __syncthreads();   // Ah[stgA] + B[s%3] ready; all warps done with prior stages

        const uint32_t aB = sa + SM_AH + (uint32_t)(stgA * A_STG);
        const uint32_t bB = sa + SM_B  + (uint32_t)((s % 3) * B_STG);

        #pragma unroll
        for (int ks = 0; ks < BK; ks += 16) {
            uint32_t bf[4][2];
            #pragma unroll
            for (int p = 0; p < 2; p++) {
                const int quad = lane >> 3;
                const int rowB = n_off + p * 16 + ((quad >> 1) & 1) * 8 + (lane & 7);
                const int colB = ks + (quad & 1) * 8;
                ldmx4(bB + (uint32_t)(rowB * ROWB + colB * 2),
                      bf[2 * p][0], bf[2 * p][1], bf[2 * p + 1][0], bf[2 * p + 1][1]);
            }
            #pragma unroll
            for (int mf = 0; mf < 2; mf++) {
                const int rowA = m_off + mf * 16 + (lane & 15);
                const int colA = ks + ((lane >> 4) & 1) * 8;
                uint32_t af[4];
                ldmx4(aB + (uint32_t)(rowA * ROWB + colA * 2), af[0], af[1], af[2], af[3]);
                #pragma unroll
                for (int nf = 0; nf < 4; nf++)
                    mma_f16(acc[mf][nf], af, bf[nf]);
            }
        }
        // no trailing sync: next iteration's __syncthreads (after its wait_group)
        // orders all readers of a stage before any overwrite (A flips each iter,
        // B ring has 3 stages).
    }

    // ---- epilogue: + bias, float2 stores ----
    float* Out = out + (size_t)n_sel * N_PTS * C_OUT + (size_t)m0 * C_OUT + n_base;
    const int r4 = lane >> 2;
    const int c2 = (lane & 3) * 2;
    #pragma unroll
    for (int mf = 0; mf < 2; mf++) {
        #pragma unroll
        for (int nf = 0; nf < 4; nf++) {
            const int col = n_off + nf * 8 + c2;
            const float bx = bs[col], by = bs[col + 1];
            const int row0 = m_off + mf * 16 + r4;
            float2 o0, o1;
            o0.x = acc[mf][nf][0] + bx; o0.y = acc[mf][nf][1] + by;
            o1.x = acc[mf][nf][2] + bx; o1.y = acc[mf][nf][3] + by;
            *reinterpret_cast<float2*>(Out + (size_t)row0 * C_OUT + col) = o0;
            *reinterpret_cast<float2*>(Out + (size_t)(row0 + 8) * C_OUT + col) = o1;
        }
    }
}

extern "C" void kernel_launch(void* const* d_in, const int* in_sizes, int n_in,
                              void* d_out, int out_size) {
    const float* x       = (const float*)d_in[0];
    const float* weight  = (const float*)d_in[1];
    const float* bias    = (const float*)d_in[2];
    const int*   indices = (const int*)d_in[3];
    const int*   t_ptr   = (n_in > 4) ? (const int*)d_in[4] : nullptr;
    float*       out     = (float*)d_out;

    {
        dim3 grid(C_OUT / 32, C_IN / 32, N_SEL);
        dim3 block(32, 8);
        wt_prep_kernel<<<grid, block>>>(weight, indices, t_ptr);
    }
    {
        cudaFuncSetAttribute(gemm_f16_kernel,
                             cudaFuncAttributeMaxDynamicSharedMemorySize, SM_TOTAL);
        dim3 grid(N_PTS / BM, C_OUT / BN, N_SEL);   // (32, 2, 192); m fastest
        dim3 block(THREADS);
        gemm_f16_kernel<<<grid, block, SM_TOTAL>>>(x, bias, indices, t_ptr, out);
    }
}

// round 9
// speedup vs baseline: 1.0392x; 1.0392x over previous
#include <cuda_runtime.h>
#include <cuda_fp16.h>
#include <cstdint>

#define N_SEL   192
#define N_PTS   2048
#define C_IN    256
#define C_OUT   256
#define N_TILES 8

#define BM 64
#define BN 256
#define BK 32
#define NSLABS (C_IN / BK)   // 8
#define THREADS 256

#define ROWB   80            // tile row bytes: 32 fp16 (64B) + 16 pad

// dynamic smem layout
#define SM_BIAS  0                         // 256 f32 = 1024 B
#define SM_AH    1024                      // 2 stages x 64 rows x 80 B
#define A_STG    (BM * ROWB)               // 5120
#define SM_B     (SM_AH + 2 * A_STG)       // 11264; 3 stages x 256 rows x 80 B
#define B_STG    (BN * ROWB)               // 20480
#define SM_TOTAL (SM_B + 3 * B_STG)        // 72704

// gathered, transposed fp16 weights: [n_sel][N=C_OUT][K=C_IN]
__device__ __half g_wt[(size_t)N_SEL * C_OUT * C_IN];

__device__ __forceinline__ uint32_t smem_u32(const void* p) {
    uint32_t a;
    asm("{ .reg .u64 t; cvta.to.shared.u64 t, %1; cvt.u32.u64 %0, t; }" : "=r"(a) : "l"(p));
    return a;
}
__device__ __forceinline__ void cp16(uint32_t dst, const void* src) {
    asm volatile("cp.async.cg.shared.global [%0], [%1], 16;" :: "r"(dst), "l"(src));
}
__device__ __forceinline__ uint32_t pack_h2(float a, float b) {
    uint32_t r;
    asm("cvt.rn.f16x2.f32 %0, %2, %1;" : "=r"(r) : "f"(a), "f"(b));
    return r;
}
__device__ __forceinline__ void ldmx4(uint32_t addr, uint32_t& r0, uint32_t& r1,
                                      uint32_t& r2, uint32_t& r3) {
    asm volatile("ldmatrix.sync.aligned.m8n8.x4.shared.b16 {%0,%1,%2,%3}, [%4];"
                 : "=r"(r0), "=r"(r1), "=r"(r2), "=r"(r3) : "r"(addr));
}
__device__ __forceinline__ void mma_f16(float* c, const uint32_t* a, const uint32_t* b) {
    asm volatile("mma.sync.aligned.m16n8k16.row.col.f32.f16.f16.f32 "
                 "{%0,%1,%2,%3}, {%4,%5,%6,%7}, {%8,%9}, {%0,%1,%2,%3};"
                 : "+f"(c[0]), "+f"(c[1]), "+f"(c[2]), "+f"(c[3])
                 : "r"(a[0]), "r"(a[1]), "r"(a[2]), "r"(a[3]), "r"(b[0]), "r"(b[1]));
}

// ---------------- kernel 1: gather + transpose + fp16 convert of W ----------------
__global__ void wt_prep_kernel(const float* __restrict__ weight,
                               const int* __restrict__ indices,
                               const int* __restrict__ t_ptr) {
    const int n = blockIdx.z;
    const int t = (t_ptr != nullptr) ? *t_ptr : 3;
    const int idx = indices[n];
    const float* W = weight + (((size_t)idx * N_TILES + t) * C_IN) * C_OUT; // [K][N]

    __shared__ float tile[32][33];
    const int tx = threadIdx.x;   // 0..31
    const int ty = threadIdx.y;   // 0..7
    const int kt = blockIdx.y * 32;
    const int nt = blockIdx.x * 32;

    #pragma unroll
    for (int j = 0; j < 4; j++) {
        const int k = kt + ty + j * 8;
        tile[ty + j * 8][tx] = W[(size_t)k * C_OUT + nt + tx];
    }
    __syncthreads();

    __half* o = g_wt + (size_t)n * C_OUT * C_IN;
    #pragma unroll
    for (int j = 0; j < 4; j++) {
        const int nn = nt + ty + j * 8;
        o[(size_t)nn * C_IN + kt + tx] = __float2half_rn(tile[tx][ty + j * 8]);
    }
}

// ---------------- kernel 2: fp16 mma.sync GEMM, pipelined convert ----------------
__global__ __launch_bounds__(THREADS, 2)
void gemm_f16_kernel(const float* __restrict__ x,
                     const float* __restrict__ bias,
                     const int* __restrict__ indices,
                     const int* __restrict__ t_ptr,
                     float* __restrict__ out) {
    extern __shared__ __align__(16) unsigned char smem[];
    const uint32_t sa = smem_u32(smem);

    const int tid  = threadIdx.x;
    const int lane = tid & 31;
    const int wid  = tid >> 5;          // 0..7

    const int n_sel = blockIdx.y;
    const int m0    = blockIdx.x * BM;
    const int t   = (t_ptr != nullptr) ? *t_ptr : 3;
    const int idx = indices[n_sel];

    const float* A = x + (size_t)n_sel * N_PTS * C_IN + (size_t)m0 * C_IN;
    const __half* Wn = g_wt + (size_t)n_sel * C_OUT * C_IN;

    // bias -> smem
    float* bs = (float*)(smem + SM_BIAS);
    if (tid < C_OUT) bs[tid] = bias[((size_t)idx * N_TILES + t) * C_OUT + tid];

    // warp tiling: 2 m-warps x 4 n-warps; warp tile 32x64
    const int m_off = (wid >> 2) * 32;
    const int n_off = (wid & 3) * 64;

    float acc[2][8][4];
    #pragma unroll
    for (int i = 0; i < 2; i++)
        #pragma unroll
        for (int j = 0; j < 8; j++)
            #pragma unroll
            for (int q = 0; q < 4; q++)
                acc[i][j][q] = 0.0f;

    // per-thread A load mapping: 256 threads -> 64 rows x 32 cols (8 floats/thread)
    const int ar  = tid >> 2;            // row 0..63
    const int as8 = (tid & 3) * 8;       // col start (floats)
    const uint32_t aSTSoff = (uint32_t)(SM_AH + ar * ROWB + (as8 >> 3) * 16);

    auto convert_A = [&](const float4& v0, const float4& v1, int stage) {
        uint4 v;
        v.x = pack_h2(v0.x, v0.y);
        v.y = pack_h2(v0.z, v0.w);
        v.z = pack_h2(v1.x, v1.y);
        v.w = pack_h2(v1.z, v1.w);
        *reinterpret_cast<uint4*>(smem + aSTSoff + stage * A_STG) = v;
    };

    // B cp.async mapping: 1024 chunks of 16B (256 rows x 4 chunks)
    auto issue_B = [&](int s) {
        const uint32_t base = sa + SM_B + (uint32_t)(s % 3) * B_STG;
        const int k0 = s * BK;
        #pragma unroll
        for (int i = 0; i < 4; i++) {
            const int c = tid + i * THREADS;
            const int r = c >> 2, seg = c & 3;
            cp16(base + (uint32_t)(r * ROWB + seg * 16),
                 Wn + (size_t)r * C_IN + k0 + seg * 8);
        }
        asm volatile("cp.async.commit_group;" ::: "memory");
    };

    // ---- prologue ----
    float4 a0, a1;   // regs holding the next A slab to convert
    {
        const float* src = A + (size_t)ar * C_IN + as8;        // slab 0
        a0 = *reinterpret_cast<const float4*>(src);
        a1 = *reinterpret_cast<const float4*>(src + 4);
    }
    issue_B(0);                   // group 0
    convert_A(a0, a1, 0);         // slab 0 -> stage 0 (no reader until barrier 0)
    {
        const float* src = A + (size_t)ar * C_IN + BK + as8;   // slab 1
        a0 = *reinterpret_cast<const float4*>(src);
        a1 = *reinterpret_cast<const float4*>(src + 4);
    }
    issue_B(1);                   // group 1

    for (int s = 0; s < NSLABS; s++) {
        if (s + 1 < NSLABS) {
            asm volatile("cp.async.wait_group 1;" ::: "memory");
        } else {
            asm volatile("cp.async.wait_group 0;" ::: "memory");
        }
        __syncthreads();   // A stage s&1 + B stage s%3 ready

        // ---- overlapped future work (writes stages not read this slab) ----
        if (s + 1 < NSLABS) {
            convert_A(a0, a1, (s + 1) & 1);
            if (s + 2 < NSLABS) {
                const float* src = A + (size_t)ar * C_IN + (s + 2) * BK + as8;
                a0 = *reinterpret_cast<const float4*>(src);
                a1 = *reinterpret_cast<const float4*>(src + 4);
                issue_B(s + 2);
            }
        }

        // ---- compute slab s ----
        const uint32_t aB = sa + SM_AH + (uint32_t)((s & 1) * A_STG);
        const uint32_t bB = sa + SM_B  + (uint32_t)((s % 3) * B_STG);

        #pragma unroll
        for (int ks = 0; ks < BK; ks += 16) {
            uint32_t bf[8][2];
            #pragma unroll
            for (int p = 0; p < 4; p++) {
                const int quad = lane >> 3;
                const int rowB = n_off + p * 16 + ((quad >> 1) & 1) * 8 + (lane & 7);
                const int colB = ks + (quad & 1) * 8;
                ldmx4(bB + (uint32_t)(rowB * ROWB + colB * 2),
                      bf[2 * p][0], bf[2 * p][1], bf[2 * p + 1][0], bf[2 * p + 1][1]);
            }
            #pragma unroll
            for (int mf = 0; mf < 2; mf++) {
                const int rowA = m_off + mf * 16 + (lane & 15);
                const int colA = ks + ((lane >> 4) & 1) * 8;
                uint32_t af[4];
                ldmx4(aB + (uint32_t)(rowA * ROWB + colA * 2), af[0], af[1], af[2], af[3]);
                #pragma unroll
                for (int nf = 0; nf < 8; nf++)
                    mma_f16(acc[mf][nf], af, bf[nf]);
            }
        }
        // stage safety: A stage written post-barrier ((s+1)&1) was last READ in
        // slab s-1 (ordered before barrier s); B stage written ((s+2)%3) was
        // last read in slab s-1 as well.
    }

    // ---- epilogue: + bias, float2 stores ----
    float* Out = out + (size_t)n_sel * N_PTS * C_OUT + (size_t)m0 * C_OUT;
    const int r4 = lane >> 2;
    const int c2 = (lane & 3) * 2;
    #pragma unroll
    for (int mf = 0; mf < 2; mf++) {
        #pragma unroll
        for (int nf = 0; nf < 8; nf++) {
            const int col = n_off + nf * 8 + c2;
            const float bx = bs[col], by = bs[col + 1];
            const int row0 = m_off + mf * 16 + r4;
            float2 o0, o1;
            o0.x = acc[mf][nf][0] + bx; o0.y = acc[mf][nf][1] + by;
            o1.x = acc[mf][nf][2] + bx; o1.y = acc[mf][nf][3] + by;
            *reinterpret_cast<float2*>(Out + (size_t)row0 * C_OUT + col) = o0;
            *reinterpret_cast<float2*>(Out + (size_t)(row0 + 8) * C_OUT + col) = o1;
        }
    }
}

extern "C" void kernel_launch(void* const* d_in, const int* in_sizes, int n_in,
                              void* d_out, int out_size) {
    const float* x       = (const float*)d_in[0];
    const float* weight  = (const float*)d_in[1];
    const float* bias    = (const float*)d_in[2];
    const int*   indices = (const int*)d_in[3];
    const int*   t_ptr   = (n_in > 4) ? (const int*)d_in[4] : nullptr;
    float*       out     = (float*)d_out;

    {
        dim3 grid(C_OUT / 32, C_IN / 32, N_SEL);
        dim3 block(32, 8);
        wt_prep_kernel<<<grid, block>>>(weight, indices, t_ptr);
    }
    {
        cudaFuncSetAttribute(gemm_f16_kernel,
                             cudaFuncAttributeMaxDynamicSharedMemorySize, SM_TOTAL);
        dim3 grid(N_PTS / BM, N_SEL);   // (32, 192); m fastest -> same-W adjacency
        dim3 block(THREADS);
        gemm_f16_kernel<<<grid, block, SM_TOTAL>>>(x, bias, indices, t_ptr, out);
    }
}